// round 3
// baseline (speedup 1.0000x reference)
#include <cuda_runtime.h>

// C-VAE (2-layer LSTM encoder + reparam + 2-layer LSTM decoder), B=128, T=256,
// D=128, Z=64, E=DC=512. Single persistent kernel, 128 blocks x 256 threads,
// custom monotonic grid barrier between the 6 dependent stages of each step.

#define BB 128
#define TT 256
#define DD 128
#define ZZ 64
#define NH 512   // hidden size for all 4 LSTMs (E = DC = 512)

// ---------------- persistent device state (scratch; no allocations) --------
__device__ float g_h[4][2][BB * NH];   // eh0, eh1, dh0, dh1 (ping-pong)
__device__ float g_c[4][BB * NH];      // cell states (in-place)
__device__ float g_encin[BB * 256];    // concat(x_t, x_t - sigmoid(c_prev))
__device__ float g_z[BB * ZZ];         // latent sample
__device__ unsigned long long g_bar = 0ULL;  // monotonic barrier counter

__device__ __forceinline__ float sigf(float x) {
    return 1.0f / (1.0f + __expf(-x));
}

// Grid-wide barrier: monotonic counter, round-up-to-multiple-of-G target.
// Safe across graph replays (no reset needed) and across launches.
__device__ __forceinline__ void gsync() {
    __syncthreads();
    if (threadIdx.x == 0) {
        __threadfence();
        unsigned long long n = atomicAdd(&g_bar, 1ULL) + 1ULL;
        unsigned long long G = (unsigned long long)gridDim.x;
        unsigned long long target = ((n + G - 1ULL) / G) * G;
        while (*((volatile unsigned long long*)&g_bar) < target) {
            __nanosleep(64);
        }
        __threadfence();
    }
    __syncthreads();
}

// ---------------- fused LSTM stage -----------------------------------------
// g = xin @ W + hprev @ U + bias;  i,f,cg,o = split4(g)
// c' = sig(f)*c + sig(i)*tanh(cg);  h' = sig(o)*tanh(c')
// Tiling: block = 32 rows x 16 hidden units (x4 gates). 4x32 = 128 tiles = grid.
// Thread = 1 row x 2 hidden x 4 gates = 8 accumulators as 4 packed f32x2.
__device__ __forceinline__ void lstm_stage(
    const float* __restrict__ xin, int kin,
    const float* __restrict__ hprev,
    const float* __restrict__ W, const float* __restrict__ U,
    const float* __restrict__ bias,
    float* __restrict__ cst, float* __restrict__ hout,
    float* sIn, float* sW)
{
    const int tid   = threadIdx.x;
    const int rbase = (blockIdx.x >> 5) << 5;   // 0,32,64,96
    const int hbase = (blockIdx.x & 31) << 4;   // 0..496 step 16
    const int rl    = tid >> 3;                 // 0..31 (local row)
    const int hg    = tid & 7;                  // 0..7  (hidden pair group)
    const int hh0   = hbase + (hg << 1);

    unsigned long long acc[4];
#pragma unroll
    for (int q = 0; q < 4; q++) {
        float2 b2 = *reinterpret_cast<const float2*>(bias + q * NH + hh0);
        asm("mov.b64 %0,{%1,%2};" : "=l"(acc[q]) : "f"(b2.x), "f"(b2.y));
    }

    auto mm = [&](const float* __restrict__ inp, int stride,
                  const float* __restrict__ M, int Kdim) {
        for (int k0 = 0; k0 < Kdim; k0 += 32) {
            __syncthreads();
            // stage 32x32 input tile (row stride 33 to dodge bank conflicts)
#pragma unroll
            for (int i = tid; i < 1024; i += 256) {
                int rr = i >> 5, kk = i & 31;
                sIn[rr * 33 + kk] = inp[(rbase + rr) * stride + k0 + kk];
            }
            // stage 32x64 weight tile, interleaved so each thread's 8 weights
            // (4 gates x 2 hid) are one contiguous 32B run:
            //   dest col c(q,j) = (j>>1)*8 + q*2 + (j&1),  j = hid offset 0..15
#pragma unroll
            for (int i = tid; i < 512; i += 256) {
                int kk = i >> 4;
                int u  = i & 15;
                int q  = u >> 2, j0 = (u & 3) << 2;
                float4 v = *reinterpret_cast<const float4*>(
                    M + (k0 + kk) * 2048 + q * NH + hbase + j0);
                float* dst = sW + kk * 64;
                int c0 = ((j0 >> 1) << 3) + (q << 1);
                dst[c0]     = v.x; dst[c0 + 1] = v.y;
                dst[c0 + 8] = v.z; dst[c0 + 9] = v.w;
            }
            __syncthreads();
#pragma unroll
            for (int kk = 0; kk < 32; kk++) {
                float a = sIn[rl * 33 + kk];
                unsigned long long a2;
                asm("mov.b64 %0,{%1,%1};" : "=l"(a2) : "f"(a));
                const ulonglong2* wp = reinterpret_cast<const ulonglong2*>(
                    sW + kk * 64 + (hg << 3));
                ulonglong2 w01 = wp[0];
                ulonglong2 w23 = wp[1];
                asm("fma.rn.f32x2 %0,%1,%2,%0;" : "+l"(acc[0]) : "l"(w01.x), "l"(a2));
                asm("fma.rn.f32x2 %0,%1,%2,%0;" : "+l"(acc[1]) : "l"(w01.y), "l"(a2));
                asm("fma.rn.f32x2 %0,%1,%2,%0;" : "+l"(acc[2]) : "l"(w23.x), "l"(a2));
                asm("fma.rn.f32x2 %0,%1,%2,%0;" : "+l"(acc[3]) : "l"(w23.y), "l"(a2));
            }
        }
    };
    mm(xin, kin, W, kin);
    mm(hprev, NH, U, NH);

    float2 g[4];
#pragma unroll
    for (int q = 0; q < 4; q++)
        asm("mov.b64 {%0,%1},%2;" : "=f"(g[q].x), "=f"(g[q].y) : "l"(acc[q]));

    const int r = rbase + rl;
#pragma unroll
    for (int e = 0; e < 2; e++) {
        float gi = e ? g[0].y : g[0].x;
        float gf = e ? g[1].y : g[1].x;
        float gc = e ? g[2].y : g[2].x;
        float go = e ? g[3].y : g[3].x;
        int idx = r * NH + hh0 + e;
        float cN = sigf(gf) * cst[idx] + sigf(gi) * tanhf(gc);
        cst[idx] = cN;
        hout[idx] = sigf(go) * tanhf(cN);
    }
}

// ---------------- latent stage: mu, log_sigma, sigma, z ---------------------
__device__ __forceinline__ void latent_stage(
    const float* __restrict__ eh1,
    const float* __restrict__ muW, const float* __restrict__ mub,
    const float* __restrict__ sgW, const float* __restrict__ sgb,
    const float* __restrict__ eps_t,
    float* __restrict__ o_mu, float* __restrict__ o_ls,
    float* __restrict__ o_sig, float* __restrict__ o_z,
    float* __restrict__ zbuf, float* sAux)
{
    const int tid = threadIdx.x;
    const int r = blockIdx.x;
    float* sEh  = sAux;        // 512 floats
    float* sred = sAux + 512;  // 384 floats

    for (int i = tid; i < NH; i += 256) sEh[i] = eh1[r * NH + i];
    __syncthreads();

    int sel  = tid >> 7;        // 0: mu, 1: log_sigma
    int half = (tid >> 6) & 1;  // K split
    int c    = tid & 63;
    const float* M = sel ? sgW : muW;
    float acc = 0.f;
    int kb = half * 256;
#pragma unroll 8
    for (int k = 0; k < 256; k++)
        acc += sEh[kb + k] * M[(kb + k) * ZZ + c];
    sred[(sel * 2 + half) * 64 + c] = acc;
    __syncthreads();

    if (tid < 128) {
        int s2 = tid >> 6, cc = tid & 63;
        float v = sred[(s2 * 2) * 64 + cc] + sred[(s2 * 2 + 1) * 64 + cc]
                + (s2 ? sgb[cc] : mub[cc]);
        sred[256 + s2 * 64 + cc] = v;
    }
    __syncthreads();

    if (tid < 64) {
        float mu = sred[256 + tid];
        float ls = sred[320 + tid];
        float sg = __expf(ls);
        float z  = mu + sg * eps_t[r * ZZ + tid];
        int o = r * ZZ + tid;
        o_mu[o] = mu; o_ls[o] = ls; o_sig[o] = sg; o_z[o] = z;
        zbuf[o] = z;
    }
}

// ---------------- output stage: c_t = sigmoid(dh1 @ out_W + b) ---------------
// Also prepares next step's encoder input.
__device__ __forceinline__ void out_stage(
    const float* __restrict__ dh1,
    const float* __restrict__ outW, const float* __restrict__ outb,
    const float* __restrict__ x,
    float* __restrict__ decoded, int tstep, float* sAux)
{
    const int tid = threadIdx.x;
    const int r = blockIdx.x;
    float* sEh  = sAux;
    float* sred = sAux + 512;

    for (int i = tid; i < NH; i += 256) sEh[i] = dh1[r * NH + i];
    __syncthreads();

    int half = tid >> 7;
    int c    = tid & 127;
    float acc = 0.f;
    int kb = half * 256;
#pragma unroll 8
    for (int k = 0; k < 256; k++)
        acc += sEh[kb + k] * outW[(kb + k) * DD + c];
    sred[half * 128 + c] = acc;
    __syncthreads();

    if (tid < 128) {
        float v = sred[tid] + sred[128 + tid] + outb[tid];
        float ct = sigf(v);
        decoded[(r * TT + tstep) * DD + tid] = ct;
        if (tstep + 1 < TT) {
            float xv = x[(r * TT + tstep + 1) * DD + tid];
            g_encin[r * 256 + tid] = xv;
            g_encin[r * 256 + 128 + tid] = xv - sigf(ct);
        }
    }
}

// ---------------- main persistent kernel ------------------------------------
__global__ void __launch_bounds__(256, 1) vae_kernel(
    const float* __restrict__ x, const float* __restrict__ eps,
    const float* __restrict__ e0W, const float* __restrict__ e0U, const float* __restrict__ e0b,
    const float* __restrict__ e1W, const float* __restrict__ e1U, const float* __restrict__ e1b,
    const float* __restrict__ muW, const float* __restrict__ mub,
    const float* __restrict__ sgW, const float* __restrict__ sgb,
    const float* __restrict__ d0W, const float* __restrict__ d0U, const float* __restrict__ d0b,
    const float* __restrict__ d1W, const float* __restrict__ d1U, const float* __restrict__ d1b,
    const float* __restrict__ oW, const float* __restrict__ ob,
    float* __restrict__ out)
{
    __shared__ __align__(16) float sIn[32 * 33];
    __shared__ __align__(16) float sW[32 * 64];
    __shared__ __align__(16) float sAux[1024];

    const int tid = threadIdx.x;

    // init: zero states read at t=0, prep encoder input for t=0 (c_prev = 0)
    {
        int r = blockIdx.x;
        for (int i = tid; i < NH; i += 256) {
#pragma unroll
            for (int s = 0; s < 4; s++) {
                g_h[s][0][r * NH + i] = 0.f;
                g_c[s][r * NH + i] = 0.f;
            }
        }
        if (tid < 128) {
            float xv = x[r * TT * DD + tid];
            g_encin[r * 256 + tid] = xv;
            g_encin[r * 256 + 128 + tid] = xv - 0.5f;  // sigmoid(0) = 0.5
        }
    }
    gsync();

    float* decoded = out;                       // [B,T,D]
    float* o_sig = out + BB * TT * DD;          // [T,B,Z]
    float* o_mu  = o_sig + TT * BB * ZZ;
    float* o_ls  = o_mu + TT * BB * ZZ;
    float* o_z   = o_ls + TT * BB * ZZ;

    for (int t = 0; t < TT; t++) {
        int po = t & 1, pn = po ^ 1;

        lstm_stage(g_encin, 256, g_h[0][po], e0W, e0U, e0b,
                   g_c[0], g_h[0][pn], sIn, sW);
        gsync();

        lstm_stage(g_h[0][pn], NH, g_h[1][po], e1W, e1U, e1b,
                   g_c[1], g_h[1][pn], sIn, sW);
        gsync();

        latent_stage(g_h[1][pn], muW, mub, sgW, sgb, eps + t * BB * ZZ,
                     o_mu + t * BB * ZZ, o_ls + t * BB * ZZ,
                     o_sig + t * BB * ZZ, o_z + t * BB * ZZ,
                     g_z, sAux);
        gsync();

        lstm_stage(g_z, ZZ, g_h[2][po], d0W, d0U, d0b,
                   g_c[2], g_h[2][pn], sIn, sW);
        gsync();

        lstm_stage(g_h[2][pn], NH, g_h[3][po], d1W, d1U, d1b,
                   g_c[3], g_h[3][pn], sIn, sW);
        gsync();

        out_stage(g_h[3][pn], oW, ob, x, decoded, t, sAux);
        gsync();
    }
}

extern "C" void kernel_launch(void* const* d_in, const int* in_sizes, int n_in,
                              void* d_out, int out_size)
{
    (void)in_sizes; (void)n_in; (void)out_size;
    vae_kernel<<<128, 256>>>(
        (const float*)d_in[0],  (const float*)d_in[1],
        (const float*)d_in[2],  (const float*)d_in[3],  (const float*)d_in[4],
        (const float*)d_in[5],  (const float*)d_in[6],  (const float*)d_in[7],
        (const float*)d_in[8],  (const float*)d_in[9],
        (const float*)d_in[10], (const float*)d_in[11],
        (const float*)d_in[12], (const float*)d_in[13], (const float*)d_in[14],
        (const float*)d_in[15], (const float*)d_in[16], (const float*)d_in[17],
        (const float*)d_in[18], (const float*)d_in[19],
        (float*)d_out);
}

// round 4
// speedup vs baseline: 1.0182x; 1.0182x over previous
#include <cuda_runtime.h>

// C-VAE (2-layer LSTM encoder + reparam + 2-layer LSTM decoder), B=128, T=256,
// D=128, Z=64, E=DC=512. Single persistent kernel, 128 blocks x 256 threads,
// custom monotonic grid barrier between the 6 dependent stages of each step.

#define BB 128
#define TT 256
#define DD 128
#define ZZ 64
#define NH 512   // hidden size for all 4 LSTMs (E = DC = 512)

// ---------------- persistent device state (scratch; no allocations) --------
__device__ float g_h[4][2][BB * NH];   // eh0, eh1, dh0, dh1 (ping-pong)
__device__ float g_c[4][BB * NH];      // cell states (in-place)
__device__ float g_encin[BB * 256];    // concat(x_t, x_t - sigmoid(c_prev))
__device__ float g_z[BB * ZZ];         // latent sample
__device__ unsigned long long g_bar = 0ULL;  // monotonic barrier counter

__device__ __forceinline__ float sigf(float x) {
    return 1.0f / (1.0f + __expf(-x));
}

// Grid-wide barrier: monotonic counter, round-up-to-multiple-of-G target.
// Safe across graph replays (no reset needed) and across launches.
__device__ __forceinline__ void gsync() {
    __syncthreads();
    if (threadIdx.x == 0) {
        __threadfence();
        unsigned long long n = atomicAdd(&g_bar, 1ULL) + 1ULL;
        unsigned long long G = (unsigned long long)gridDim.x;
        unsigned long long target = ((n + G - 1ULL) / G) * G;
        while (*((volatile unsigned long long*)&g_bar) < target) {
            __nanosleep(64);
        }
        __threadfence();
    }
    __syncthreads();
}

// ---------------- fused LSTM stage -----------------------------------------
// g = xin @ W + hprev @ U + bias;  i,f,cg,o = split4(g)
// c' = sig(f)*c + sig(i)*tanh(cg);  h' = sig(o)*tanh(c')
// Tiling: block = 32 rows x 16 hidden units (x4 gates). 4x32 = 128 tiles = grid.
// Thread = 1 row x 2 hidden x 4 gates = 8 accumulators as 4 packed f32x2.
__device__ __forceinline__ void lstm_stage(
    const float* __restrict__ xin, int kin,
    const float* __restrict__ hprev,
    const float* __restrict__ W, const float* __restrict__ U,
    const float* __restrict__ bias,
    float* __restrict__ cst, float* __restrict__ hout,
    float* sIn, float* sW)
{
    const int tid   = threadIdx.x;
    const int rbase = (blockIdx.x >> 5) << 5;   // 0,32,64,96
    const int hbase = (blockIdx.x & 31) << 4;   // 0..496 step 16
    const int rl    = tid >> 3;                 // 0..31 (local row)
    const int hg    = tid & 7;                  // 0..7  (hidden pair group)
    const int hh0   = hbase + (hg << 1);

    unsigned long long acc[4];
#pragma unroll
    for (int q = 0; q < 4; q++) {
        float2 b2 = *reinterpret_cast<const float2*>(bias + q * NH + hh0);
        asm("mov.b64 %0,{%1,%2};" : "=l"(acc[q]) : "f"(b2.x), "f"(b2.y));
    }

    auto mm = [&](const float* __restrict__ inp, int stride,
                  const float* __restrict__ M, int Kdim) {
        for (int k0 = 0; k0 < Kdim; k0 += 32) {
            __syncthreads();
            // stage 32x32 input tile (row stride 33 to dodge bank conflicts)
#pragma unroll
            for (int i = tid; i < 1024; i += 256) {
                int rr = i >> 5, kk = i & 31;
                sIn[rr * 33 + kk] = inp[(rbase + rr) * stride + k0 + kk];
            }
            // stage 32x64 weight tile, interleaved so each thread's 8 weights
            // (4 gates x 2 hid) are one contiguous 32B run:
            //   dest col c(q,j) = (j>>1)*8 + q*2 + (j&1),  j = hid offset 0..15
#pragma unroll
            for (int i = tid; i < 512; i += 256) {
                int kk = i >> 4;
                int u  = i & 15;
                int q  = u >> 2, j0 = (u & 3) << 2;
                float4 v = *reinterpret_cast<const float4*>(
                    M + (k0 + kk) * 2048 + q * NH + hbase + j0);
                float* dst = sW + kk * 64;
                int c0 = ((j0 >> 1) << 3) + (q << 1);
                dst[c0]     = v.x; dst[c0 + 1] = v.y;
                dst[c0 + 8] = v.z; dst[c0 + 9] = v.w;
            }
            __syncthreads();
#pragma unroll
            for (int kk = 0; kk < 32; kk++) {
                float a = sIn[rl * 33 + kk];
                unsigned long long a2;
                asm("mov.b64 %0,{%1,%1};" : "=l"(a2) : "f"(a));
                const ulonglong2* wp = reinterpret_cast<const ulonglong2*>(
                    sW + kk * 64 + (hg << 3));
                ulonglong2 w01 = wp[0];
                ulonglong2 w23 = wp[1];
                asm("fma.rn.f32x2 %0,%1,%2,%0;" : "+l"(acc[0]) : "l"(w01.x), "l"(a2));
                asm("fma.rn.f32x2 %0,%1,%2,%0;" : "+l"(acc[1]) : "l"(w01.y), "l"(a2));
                asm("fma.rn.f32x2 %0,%1,%2,%0;" : "+l"(acc[2]) : "l"(w23.x), "l"(a2));
                asm("fma.rn.f32x2 %0,%1,%2,%0;" : "+l"(acc[3]) : "l"(w23.y), "l"(a2));
            }
        }
    };
    mm(xin, kin, W, kin);
    mm(hprev, NH, U, NH);

    float2 g[4];
#pragma unroll
    for (int q = 0; q < 4; q++)
        asm("mov.b64 {%0,%1},%2;" : "=f"(g[q].x), "=f"(g[q].y) : "l"(acc[q]));

    const int r = rbase + rl;
#pragma unroll
    for (int e = 0; e < 2; e++) {
        float gi = e ? g[0].y : g[0].x;
        float gf = e ? g[1].y : g[1].x;
        float gc = e ? g[2].y : g[2].x;
        float go = e ? g[3].y : g[3].x;
        int idx = r * NH + hh0 + e;
        float cN = sigf(gf) * cst[idx] + sigf(gi) * tanhf(gc);
        cst[idx] = cN;
        hout[idx] = sigf(go) * tanhf(cN);
    }
}

// ---------------- latent stage: mu, log_sigma, sigma, z ---------------------
__device__ __forceinline__ void latent_stage(
    const float* __restrict__ eh1,
    const float* __restrict__ muW, const float* __restrict__ mub,
    const float* __restrict__ sgW, const float* __restrict__ sgb,
    const float* __restrict__ eps_t,
    float* __restrict__ o_mu, float* __restrict__ o_ls,
    float* __restrict__ o_sig, float* __restrict__ o_z,
    float* __restrict__ zbuf, float* sAux)
{
    const int tid = threadIdx.x;
    const int r = blockIdx.x;
    float* sEh  = sAux;        // 512 floats
    float* sred = sAux + 512;  // 384 floats

    for (int i = tid; i < NH; i += 256) sEh[i] = eh1[r * NH + i];
    __syncthreads();

    int sel  = tid >> 7;        // 0: mu, 1: log_sigma
    int half = (tid >> 6) & 1;  // K split
    int c    = tid & 63;
    const float* M = sel ? sgW : muW;
    float acc = 0.f;
    int kb = half * 256;
#pragma unroll 8
    for (int k = 0; k < 256; k++)
        acc += sEh[kb + k] * M[(kb + k) * ZZ + c];
    sred[(sel * 2 + half) * 64 + c] = acc;
    __syncthreads();

    if (tid < 128) {
        int s2 = tid >> 6, cc = tid & 63;
        float v = sred[(s2 * 2) * 64 + cc] + sred[(s2 * 2 + 1) * 64 + cc]
                + (s2 ? sgb[cc] : mub[cc]);
        sred[256 + s2 * 64 + cc] = v;
    }
    __syncthreads();

    if (tid < 64) {
        float mu = sred[256 + tid];
        float ls = sred[320 + tid];
        float sg = __expf(ls);
        float z  = mu + sg * eps_t[r * ZZ + tid];
        int o = r * ZZ + tid;
        o_mu[o] = mu; o_ls[o] = ls; o_sig[o] = sg; o_z[o] = z;
        zbuf[o] = z;
    }
}

// ---------------- output stage: c_t = sigmoid(dh1 @ out_W + b) ---------------
// Also prepares next step's encoder input.
__device__ __forceinline__ void out_stage(
    const float* __restrict__ dh1,
    const float* __restrict__ outW, const float* __restrict__ outb,
    const float* __restrict__ x,
    float* __restrict__ decoded, int tstep, float* sAux)
{
    const int tid = threadIdx.x;
    const int r = blockIdx.x;
    float* sEh  = sAux;
    float* sred = sAux + 512;

    for (int i = tid; i < NH; i += 256) sEh[i] = dh1[r * NH + i];
    __syncthreads();

    int half = tid >> 7;
    int c    = tid & 127;
    float acc = 0.f;
    int kb = half * 256;
#pragma unroll 8
    for (int k = 0; k < 256; k++)
        acc += sEh[kb + k] * outW[(kb + k) * DD + c];
    sred[half * 128 + c] = acc;
    __syncthreads();

    if (tid < 128) {
        float v = sred[tid] + sred[128 + tid] + outb[tid];
        float ct = sigf(v);
        decoded[(r * TT + tstep) * DD + tid] = ct;
        if (tstep + 1 < TT) {
            float xv = x[(r * TT + tstep + 1) * DD + tid];
            g_encin[r * 256 + tid] = xv;
            g_encin[r * 256 + 128 + tid] = xv - sigf(ct);
        }
    }
}

// ---------------- main persistent kernel ------------------------------------
__global__ void __launch_bounds__(256, 1) vae_kernel(
    const float* __restrict__ x, const float* __restrict__ eps,
    const float* __restrict__ e0W, const float* __restrict__ e0U, const float* __restrict__ e0b,
    const float* __restrict__ e1W, const float* __restrict__ e1U, const float* __restrict__ e1b,
    const float* __restrict__ muW, const float* __restrict__ mub,
    const float* __restrict__ sgW, const float* __restrict__ sgb,
    const float* __restrict__ d0W, const float* __restrict__ d0U, const float* __restrict__ d0b,
    const float* __restrict__ d1W, const float* __restrict__ d1U, const float* __restrict__ d1b,
    const float* __restrict__ oW, const float* __restrict__ ob,
    float* __restrict__ out)
{
    __shared__ __align__(16) float sIn[32 * 33];
    __shared__ __align__(16) float sW[32 * 64];
    __shared__ __align__(16) float sAux[1024];

    const int tid = threadIdx.x;

    // init: zero states read at t=0, prep encoder input for t=0 (c_prev = 0)
    {
        int r = blockIdx.x;
        for (int i = tid; i < NH; i += 256) {
#pragma unroll
            for (int s = 0; s < 4; s++) {
                g_h[s][0][r * NH + i] = 0.f;
                g_c[s][r * NH + i] = 0.f;
            }
        }
        if (tid < 128) {
            float xv = x[r * TT * DD + tid];
            g_encin[r * 256 + tid] = xv;
            g_encin[r * 256 + 128 + tid] = xv - 0.5f;  // sigmoid(0) = 0.5
        }
    }
    gsync();

    float* decoded = out;                       // [B,T,D]
    float* o_sig = out + BB * TT * DD;          // [T,B,Z]
    float* o_mu  = o_sig + TT * BB * ZZ;
    float* o_ls  = o_mu + TT * BB * ZZ;
    float* o_z   = o_ls + TT * BB * ZZ;

    for (int t = 0; t < TT; t++) {
        int po = t & 1, pn = po ^ 1;

        lstm_stage(g_encin, 256, g_h[0][po], e0W, e0U, e0b,
                   g_c[0], g_h[0][pn], sIn, sW);
        gsync();

        lstm_stage(g_h[0][pn], NH, g_h[1][po], e1W, e1U, e1b,
                   g_c[1], g_h[1][pn], sIn, sW);
        gsync();

        latent_stage(g_h[1][pn], muW, mub, sgW, sgb, eps + t * BB * ZZ,
                     o_mu + t * BB * ZZ, o_ls + t * BB * ZZ,
                     o_sig + t * BB * ZZ, o_z + t * BB * ZZ,
                     g_z, sAux);
        gsync();

        lstm_stage(g_z, ZZ, g_h[2][po], d0W, d0U, d0b,
                   g_c[2], g_h[2][pn], sIn, sW);
        gsync();

        lstm_stage(g_h[2][pn], NH, g_h[3][po], d1W, d1U, d1b,
                   g_c[3], g_h[3][pn], sIn, sW);
        gsync();

        out_stage(g_h[3][pn], oW, ob, x, decoded, t, sAux);
        gsync();
    }
}

extern "C" void kernel_launch(void* const* d_in, const int* in_sizes, int n_in,
                              void* d_out, int out_size)
{
    (void)in_sizes; (void)n_in; (void)out_size;
    vae_kernel<<<128, 256>>>(
        (const float*)d_in[0],  (const float*)d_in[1],
        (const float*)d_in[2],  (const float*)d_in[3],  (const float*)d_in[4],
        (const float*)d_in[5],  (const float*)d_in[6],  (const float*)d_in[7],
        (const float*)d_in[8],  (const float*)d_in[9],
        (const float*)d_in[10], (const float*)d_in[11],
        (const float*)d_in[12], (const float*)d_in[13], (const float*)d_in[14],
        (const float*)d_in[15], (const float*)d_in[16], (const float*)d_in[17],
        (const float*)d_in[18], (const float*)d_in[19],
        (float*)d_out);
}

// round 5
// speedup vs baseline: 2.1639x; 2.1252x over previous
#include <cuda_runtime.h>

#define BB 128
#define TT 256
#define DD 128
#define ZZ 64
#define NH 512

// ---------------- persistent device state (no allocations) ------------------
__device__ float g_h[4][2][BB * NH];     // eh0, eh1, dh0, dh1 (ping-pong)
__device__ float g_c[4][BB * NH];        // cell states (in-place)
__device__ float g_encin[BB * 256];      // concat(x_t, x_t - sigmoid(c_prev))
__device__ float g_wr[3392 * 2048];      // reordered combined [W;U] weights
__device__ unsigned long long g_bar = 0ULL;

__device__ __forceinline__ float sigf(float x) {
    return 1.0f / (1.0f + __expf(-x));
}

// Grid-wide barrier: monotonic counter (safe across graph replays).
__device__ __forceinline__ void gsync() {
    __syncthreads();
    if (threadIdx.x == 0) {
        __threadfence();
        unsigned long long n = atomicAdd(&g_bar, 1ULL) + 1ULL;
        unsigned long long G = (unsigned long long)gridDim.x;
        unsigned long long target = ((n + G - 1ULL) / G) * G;
        while (*((volatile unsigned long long*)&g_bar) < target) {
            __nanosleep(32);
        }
        __threadfence();
    }
    __syncthreads();
}

// ---------------- fused LSTM stage ------------------------------------------
// 512 threads: half 0 does even K-tiles, half 1 odd K-tiles of the combined
// [xin@W ; hprev@U] reduction; partials merged via smem at the end.
// Double-buffered smem staging (LDG->reg during compute, STS after, 1 sync).
// Weights pre-reordered in g_wr: per 64-col block segment, layout
//   [ lo16B(hg=0..7) | hi16B(hg=0..7) ]  -> conflict-free LDS.128.
__device__ __forceinline__ void lstm_stage(
    const float* __restrict__ xin, int kin,
    const float* __restrict__ hprev,
    const float* __restrict__ Gr,
    const float* __restrict__ bias,
    float* __restrict__ cst, float* __restrict__ hout,
    float* smemPool,
    bool zmode,
    const float* __restrict__ mu_t, const float* __restrict__ ls_t,
    const float* __restrict__ eps_t,
    float* __restrict__ sig_t, float* __restrict__ z_t)
{
    const int tid   = threadIdx.x;
    const int half  = tid >> 8;
    const int t2    = tid & 255;
    const int rbase = (blockIdx.x >> 5) << 5;   // 0,32,64,96
    const int seg   = blockIdx.x & 31;          // 64-col weight segment
    const int hbase = seg << 4;                 // hidden base (16 per block)
    const int rl    = t2 >> 3;                  // 0..31 local row
    const int hg    = t2 & 7;                   // 0..7 hidden-pair
    const int hh0   = hbase + (hg << 1);

    float* sInB = smemPool + half * 2304;          // 2 bufs x 1152
    float* sWB  = smemPool + 4608 + half * 4096;   // 2 bufs x 2048
    float* ex   = smemPool + 8704;                 // exchange (= half1 sW buf0)

    // staging index precompute
    const int srr = t2 >> 3, sc4 = t2 & 7;     // sIn: row, float4-col
    const int wkk = t2 >> 4, wf4 = t2 & 15;    // sW: kk, float4-col

    float4 rIn, rW0, rW1;

    auto do_load = [&](int v) {
        int k0 = v << 5;
        if (k0 < kin) {
            if (!zmode) {
                rIn = *reinterpret_cast<const float4*>(
                    xin + (rbase + srr) * kin + k0 + (sc4 << 2));
            } else {
                // dec0: build z = mu + exp(ls)*eps on the fly
                int rg = rbase + srr;
                int col = k0 + (sc4 << 2);
                float4 m4 = *reinterpret_cast<const float4*>(mu_t + rg * ZZ + col);
                float4 l4 = *reinterpret_cast<const float4*>(ls_t + rg * ZZ + col);
                float4 e4 = *reinterpret_cast<const float4*>(eps_t + rg * ZZ + col);
                float4 s4, z4;
                s4.x = __expf(l4.x); s4.y = __expf(l4.y);
                s4.z = __expf(l4.z); s4.w = __expf(l4.w);
                z4.x = fmaf(s4.x, e4.x, m4.x);
                z4.y = fmaf(s4.y, e4.y, m4.y);
                z4.z = fmaf(s4.z, e4.z, m4.z);
                z4.w = fmaf(s4.w, e4.w, m4.w);
                if (seg == 0) {
                    *reinterpret_cast<float4*>(sig_t + rg * ZZ + col) = s4;
                    *reinterpret_cast<float4*>(z_t + rg * ZZ + col) = z4;
                }
                rIn = z4;
            }
        } else {
            rIn = *reinterpret_cast<const float4*>(
                hprev + (rbase + srr) * NH + (k0 - kin) + (sc4 << 2));
        }
        const float* wsrc = Gr + ((k0 + wkk) << 11) + (seg << 6) + (wf4 << 2);
        rW0 = *reinterpret_cast<const float4*>(wsrc);
        rW1 = *reinterpret_cast<const float4*>(wsrc + (16 << 11));
    };

    auto do_store = [&](float* bIn, float* bW) {
        *reinterpret_cast<float4*>(bIn + srr * 36 + (sc4 << 2)) = rIn;
        *reinterpret_cast<float4*>(bW + (wkk << 6) + (wf4 << 2)) = rW0;
        *reinterpret_cast<float4*>(bW + ((wkk + 16) << 6) + (wf4 << 2)) = rW1;
    };

    unsigned long long acc[4];
    if (half == 0) {
#pragma unroll
        for (int q = 0; q < 4; q++) {
            float2 b2 = *reinterpret_cast<const float2*>(bias + q * NH + hh0);
            asm("mov.b64 %0,{%1,%2};" : "=l"(acc[q]) : "f"(b2.x), "f"(b2.y));
        }
    } else {
#pragma unroll
        for (int q = 0; q < 4; q++) acc[q] = 0ULL;
    }

    const int nt = (kin + NH) >> 5;   // even for all stages (24,32,18,32)
    const int nm = nt >> 1;           // tiles per half

    do_load(half);
    do_store(sInB, sWB);
    __syncthreads();

    int p = 0;
    for (int i = 0; i < nm; i++) {
        if (i + 1 < nm) do_load(half + ((i + 1) << 1));
        const float* bIn = sInB + p * 1152;
        const float* bW  = sWB + p * 2048;
#pragma unroll
        for (int k4 = 0; k4 < 8; k4++) {
            float4 a4 = *reinterpret_cast<const float4*>(bIn + rl * 36 + (k4 << 2));
#pragma unroll
            for (int j = 0; j < 4; j++) {
                float a = (j == 0) ? a4.x : (j == 1) ? a4.y : (j == 2) ? a4.z : a4.w;
                unsigned long long a2;
                asm("mov.b64 %0,{%1,%1};" : "=l"(a2) : "f"(a));
                const float* wr = bW + (((k4 << 2) + j) << 6) + (hg << 2);
                ulonglong2 w01 = *reinterpret_cast<const ulonglong2*>(wr);
                ulonglong2 w23 = *reinterpret_cast<const ulonglong2*>(wr + 32);
                asm("fma.rn.f32x2 %0,%1,%2,%0;" : "+l"(acc[0]) : "l"(w01.x), "l"(a2));
                asm("fma.rn.f32x2 %0,%1,%2,%0;" : "+l"(acc[1]) : "l"(w01.y), "l"(a2));
                asm("fma.rn.f32x2 %0,%1,%2,%0;" : "+l"(acc[2]) : "l"(w23.x), "l"(a2));
                asm("fma.rn.f32x2 %0,%1,%2,%0;" : "+l"(acc[3]) : "l"(w23.y), "l"(a2));
            }
        }
        if (i + 1 < nm) do_store(sInB + (p ^ 1) * 1152, sWB + (p ^ 1) * 2048);
        __syncthreads();
        p ^= 1;
    }

    // merge halves + epilogue
    if (half) {
        unsigned long long* exu = reinterpret_cast<unsigned long long*>(ex);
#pragma unroll
        for (int q = 0; q < 4; q++) exu[t2 * 4 + q] = acc[q];
    }
    __syncthreads();
    if (!half) {
        const unsigned long long* exu = reinterpret_cast<const unsigned long long*>(ex);
#pragma unroll
        for (int q = 0; q < 4; q++) {
            unsigned long long o = exu[t2 * 4 + q];
            asm("add.rn.f32x2 %0,%0,%1;" : "+l"(acc[q]) : "l"(o));
        }
        float2 gg[4];
#pragma unroll
        for (int q = 0; q < 4; q++)
            asm("mov.b64 {%0,%1},%2;" : "=f"(gg[q].x), "=f"(gg[q].y) : "l"(acc[q]));
        const int r = rbase + rl;
#pragma unroll
        for (int e = 0; e < 2; e++) {
            float gi = e ? gg[0].y : gg[0].x;
            float gf = e ? gg[1].y : gg[1].x;
            float gc = e ? gg[2].y : gg[2].x;
            float go = e ? gg[3].y : gg[3].x;
            int idx = r * NH + hh0 + e;
            float cN = sigf(gf) * cst[idx] + sigf(gi) * tanhf(gc);
            cst[idx] = cN;
            hout[idx] = sigf(go) * tanhf(cN);
        }
    }
}

// ---------------- latent: mu / log_sigma (column-sliced) --------------------
// Block: 32 rows x 4 output cols (of combined 128 = mu 64 | ls 64).
__device__ __forceinline__ void latent_stage(
    const float* __restrict__ eh1,
    const float* __restrict__ muW, const float* __restrict__ mub,
    const float* __restrict__ sgW, const float* __restrict__ sgb,
    float* __restrict__ mu_t, float* __restrict__ ls_t, float* sAux)
{
    const int tid = threadIdx.x;
    const int rb = (blockIdx.x >> 5) << 5;
    const int cg = blockIdx.x & 31;
    const float* M; const float* bv; float* op; int cb;
    if (cg < 16) { M = muW; bv = mub; op = mu_t; cb = cg << 2; }
    else         { M = sgW; bv = sgb; op = ls_t; cb = (cg - 16) << 2; }
    const int r = tid >> 4, c2 = (tid >> 2) & 3, ks = tid & 3;
    const float* ar = eh1 + (rb + r) * NH + (ks << 7);
    const float* wc = M + ((ks << 7) * ZZ) + cb + c2;
    float acc = 0.f;
#pragma unroll 16
    for (int k = 0; k < 128; k++) acc = fmaf(ar[k], wc[k * ZZ], acc);
    sAux[tid] = acc;
    __syncthreads();
    if (tid < 128) {
        int r2 = tid >> 2, cc = tid & 3;
        int b0 = (r2 << 4) + (cc << 2);
        float v = sAux[b0] + sAux[b0 + 1] + sAux[b0 + 2] + sAux[b0 + 3]
                + bv[cb + cc];
        op[(rb + r2) * ZZ + cb + cc] = v;
    }
}

// ---------------- output: c_t = sigmoid(dh1 @ out_W + b) (column-sliced) ----
__device__ __forceinline__ void out_stage(
    const float* __restrict__ dh1,
    const float* __restrict__ oW, const float* __restrict__ ob,
    const float* __restrict__ x,
    float* __restrict__ decoded, int t, float* sAux)
{
    const int tid = threadIdx.x;
    const int rb = (blockIdx.x >> 5) << 5;
    const int cb = (blockIdx.x & 31) << 2;
    const int r = tid >> 4, c2 = (tid >> 2) & 3, ks = tid & 3;
    const float* ar = dh1 + (rb + r) * NH + (ks << 7);
    const float* wc = oW + ((ks << 7) * DD) + cb + c2;
    float acc = 0.f;
#pragma unroll 16
    for (int k = 0; k < 128; k++) acc = fmaf(ar[k], wc[k * DD], acc);
    sAux[tid] = acc;
    __syncthreads();
    if (tid < 128) {
        int r2 = tid >> 2, cc = tid & 3;
        int b0 = (r2 << 4) + (cc << 2);
        float v = sAux[b0] + sAux[b0 + 1] + sAux[b0 + 2] + sAux[b0 + 3]
                + ob[cb + cc];
        float ct = sigf(v);
        int rg = rb + r2, col = cb + cc;
        decoded[(rg * TT + t) * DD + col] = ct;
        if (t + 1 < TT) {
            float xv = x[(rg * TT + t + 1) * DD + col];
            g_encin[rg * 256 + col] = xv;
            g_encin[rg * 256 + DD + col] = xv - sigf(ct);
        }
    }
}

// ---------------- main persistent kernel ------------------------------------
__global__ void __launch_bounds__(512, 1) vae_kernel(
    const float* __restrict__ x, const float* __restrict__ eps,
    const float* __restrict__ e0W, const float* __restrict__ e0U, const float* __restrict__ e0b,
    const float* __restrict__ e1W, const float* __restrict__ e1U, const float* __restrict__ e1b,
    const float* __restrict__ muW, const float* __restrict__ mub,
    const float* __restrict__ sgW, const float* __restrict__ sgb,
    const float* __restrict__ d0W, const float* __restrict__ d0U, const float* __restrict__ d0b,
    const float* __restrict__ d1W, const float* __restrict__ d1U, const float* __restrict__ d1b,
    const float* __restrict__ oW, const float* __restrict__ ob,
    float* __restrict__ out)
{
    extern __shared__ float smemPool[];
    const int tid = threadIdx.x;

    // ---- one-time weight reorder into bank-conflict-free combined layout ----
    // src col = q*512 + p*2 + e  ->  dst col' = (p>>3)*64 + (q>>1)*32
    //                                          + (p&7)*4 + (q&1)*2 + e
    {
        const float* srcs[8] = {e0W, e0U, e1W, e1U, d0W, d0U, d1W, d1U};
        const int rws[8] = {256, 512, 512, 512, 64, 512, 512, 512};
        int gt = blockIdx.x * 512 + tid;
        int base = 0;
        for (int s = 0; s < 8; s++) {
            const float* S = srcs[s];
            int n = rws[s] << 11;
            for (int idx = gt; idx < n; idx += 65536) {
                int row = idx >> 11, cp = idx & 2047;
                int sg = cp >> 6, w = cp & 63;
                int m = w >> 5, r5 = w & 31;
                int hg2 = r5 >> 2, lo2 = r5 & 3;
                int q = (m << 1) + (lo2 >> 1), e = lo2 & 1;
                int pp = (sg << 3) + hg2;
                g_wr[((base + row) << 11) + cp] =
                    S[(row << 11) + q * NH + (pp << 1) + e];
            }
            base += rws[s];
        }
    }

    // ---- init states + t=0 encoder input ----
    {
        int r = blockIdx.x;
        for (int i = tid; i < NH; i += 512) {
#pragma unroll
            for (int s = 0; s < 4; s++) {
                g_h[s][0][r * NH + i] = 0.f;
                g_c[s][r * NH + i] = 0.f;
            }
        }
        if (tid < DD) {
            float xv = x[r * TT * DD + tid];
            g_encin[r * 256 + tid] = xv;
            g_encin[r * 256 + DD + tid] = xv - 0.5f;   // sigmoid(0)=0.5
        }
    }
    gsync();

    float* decoded = out;                         // [B,T,D]
    float* o_sig = out + BB * TT * DD;            // [T,B,Z]
    float* o_mu  = o_sig + TT * BB * ZZ;
    float* o_ls  = o_mu + TT * BB * ZZ;
    float* o_z   = o_ls + TT * BB * ZZ;

    const float* Gr_e0 = g_wr;
    const float* Gr_e1 = g_wr + 768 * 2048;
    const float* Gr_d0 = g_wr + 1792 * 2048;
    const float* Gr_d1 = g_wr + 2368 * 2048;

    float* sAux = smemPool + 12800;

    for (int t = 0; t < TT; t++) {
        int po = t & 1, pn = po ^ 1;
        float* mu_t = o_mu + t * BB * ZZ;
        float* ls_t = o_ls + t * BB * ZZ;
        float* sg_t = o_sig + t * BB * ZZ;
        float* z_t  = o_z + t * BB * ZZ;

        lstm_stage(g_encin, 256, g_h[0][po], Gr_e0, e0b,
                   g_c[0], g_h[0][pn], smemPool,
                   false, 0, 0, 0, 0, 0);
        gsync();

        lstm_stage(g_h[0][pn], 512, g_h[1][po], Gr_e1, e1b,
                   g_c[1], g_h[1][pn], smemPool,
                   false, 0, 0, 0, 0, 0);
        gsync();

        latent_stage(g_h[1][pn], muW, mub, sgW, sgb, mu_t, ls_t, sAux);
        gsync();

        lstm_stage(0, 64, g_h[2][po], Gr_d0, d0b,
                   g_c[2], g_h[2][pn], smemPool,
                   true, mu_t, ls_t, eps + t * BB * ZZ, sg_t, z_t);
        gsync();

        lstm_stage(g_h[2][pn], 512, g_h[3][po], Gr_d1, d1b,
                   g_c[3], g_h[3][pn], smemPool,
                   false, 0, 0, 0, 0, 0);
        gsync();

        out_stage(g_h[3][pn], oW, ob, x, decoded, t, sAux);
        gsync();
    }
}

extern "C" void kernel_launch(void* const* d_in, const int* in_sizes, int n_in,
                              void* d_out, int out_size)
{
    (void)in_sizes; (void)n_in; (void)out_size;
    const int smemBytes = 13312 * 4;   // 53248 B dynamic smem
    cudaFuncSetAttribute(vae_kernel,
                         cudaFuncAttributeMaxDynamicSharedMemorySize, smemBytes);
    vae_kernel<<<128, 512, smemBytes>>>(
        (const float*)d_in[0],  (const float*)d_in[1],
        (const float*)d_in[2],  (const float*)d_in[3],  (const float*)d_in[4],
        (const float*)d_in[5],  (const float*)d_in[6],  (const float*)d_in[7],
        (const float*)d_in[8],  (const float*)d_in[9],
        (const float*)d_in[10], (const float*)d_in[11],
        (const float*)d_in[12], (const float*)d_in[13], (const float*)d_in[14],
        (const float*)d_in[15], (const float*)d_in[16], (const float*)d_in[17],
        (const float*)d_in[18], (const float*)d_in[19],
        (float*)d_out);
}

// round 10
// speedup vs baseline: 2.8710x; 1.3268x over previous
#include <cuda_runtime.h>

#define BB 128
#define TT 256
#define DD 128
#define ZZ 64
#define NH 512

typedef unsigned long long ull;

// ---------------- persistent device state (no allocations) ------------------
__device__ float g_h[4][2][BB * NH];     // eh0, eh1, dh0, dh1 (ping-pong)
__device__ float g_c[4][BB * NH];        // cell states (in-place)
__device__ float g_encin[BB * 256];      // concat(x_t, x_t - sigmoid(c_prev))
__device__ float g_wr[3392 * 2048];      // reordered combined [W;U] weights
__device__ ull g_bar = 0ULL;

__device__ __forceinline__ float sigf(float x) {
    return 1.0f / (1.0f + __expf(-x));
}

__device__ __forceinline__ void gsync() {
    __syncthreads();
    if (threadIdx.x == 0) {
        __threadfence();
        ull n = atomicAdd(&g_bar, 1ULL) + 1ULL;
        ull G = (ull)gridDim.x;
        ull target = ((n + G - 1ULL) / G) * G;
        while (*((volatile ull*)&g_bar) < target) {
            __nanosleep(32);
        }
        __threadfence();
    }
    __syncthreads();
}

#define FMA2(acc, w, a) \
    asm("fma.rn.f32x2 %0,%1,%2,%0;" : "+l"(acc) : "l"(w), "l"(a))

// ---------------- fused LSTM stage ------------------------------------------
// Block tile: 32 rows x 64 gate-cols (16 hidden x 4 gates). Grid = 4x32 = 128.
// 512 threads = 4 K-quarters x 128 threads. Thread tile: 4 rows x 1 hidden x
// 4 gates = 8 f32x2 accumulators. Weights packed [hidden][gate] (16B/lane),
// inputs staged transposed + duplicated {a,a} for direct f32x2 broadcast.
__device__ __forceinline__ void lstm_stage(
    const float* __restrict__ xin, int kin,
    const float* __restrict__ hprev,
    const float* __restrict__ Gr,
    const float* __restrict__ bias,
    float* __restrict__ cst, float* __restrict__ hout,
    float* smemPool,
    bool zmode,
    const float* __restrict__ mu_t, const float* __restrict__ ls_t,
    const float* __restrict__ eps_t,
    float* __restrict__ sig_t, float* __restrict__ z_t)
{
    const int tid   = threadIdx.x;
    const int q     = tid >> 7;       // K-quarter 0..3
    const int tq    = tid & 127;
    const int rbase = (blockIdx.x >> 5) << 5;   // 0,32,64,96
    const int seg   = blockIdx.x & 31;          // 64-col weight segment
    const int hb    = seg << 4;                 // hidden base
    // compute mapping
    const int c  = tq & 15;          // hidden unit 0..15
    const int rg = tq >> 4;          // row group 0..7 (4 rows each)
    // staging mapping
    const int fi  = tq & 15;         // w: float4 col 0..15
    const int wk  = tq >> 4;         // w: kk base 0..7
    const int row = tq & 31;         // a: row 0..31
    const int kh  = tq >> 5;         // a: k-chunk 0..3

    float* wB = smemPool + (q << 13);                  // 2 bufs x 2048 floats
    ull*   aB = (ull*)(smemPool + (q << 13) + 4096);   // 2 bufs x 1024 u64

    float4 rw0, rw1, rw2, rw3, ra0, ra1;

    auto do_load = [&](int v) {
        int k0 = v << 5;
        const float* ws = Gr + (k0 + wk) * 2048 + (seg << 6) + (fi << 2);
        rw0 = *reinterpret_cast<const float4*>(ws);
        rw1 = *reinterpret_cast<const float4*>(ws + 8 * 2048);
        rw2 = *reinterpret_cast<const float4*>(ws + 16 * 2048);
        rw3 = *reinterpret_cast<const float4*>(ws + 24 * 2048);
        if (k0 < kin) {
            if (!zmode) {
                const float* s = xin + (rbase + row) * kin + k0 + (kh << 3);
                ra0 = *reinterpret_cast<const float4*>(s);
                ra1 = *reinterpret_cast<const float4*>(s + 4);
            } else {
                int rglob = rbase + row;
                int ks = k0 + (kh << 3);
                const float* mp = mu_t + rglob * ZZ + ks;
                const float* lp = ls_t + rglob * ZZ + ks;
                const float* ep = eps_t + rglob * ZZ + ks;
                float4 m0 = *reinterpret_cast<const float4*>(mp);
                float4 m1 = *reinterpret_cast<const float4*>(mp + 4);
                float4 l0 = *reinterpret_cast<const float4*>(lp);
                float4 l1 = *reinterpret_cast<const float4*>(lp + 4);
                float4 e0 = *reinterpret_cast<const float4*>(ep);
                float4 e1 = *reinterpret_cast<const float4*>(ep + 4);
                float4 s0, s1, z0, z1;
                s0.x = __expf(l0.x); s0.y = __expf(l0.y);
                s0.z = __expf(l0.z); s0.w = __expf(l0.w);
                s1.x = __expf(l1.x); s1.y = __expf(l1.y);
                s1.z = __expf(l1.z); s1.w = __expf(l1.w);
                z0.x = fmaf(s0.x, e0.x, m0.x); z0.y = fmaf(s0.y, e0.y, m0.y);
                z0.z = fmaf(s0.z, e0.z, m0.z); z0.w = fmaf(s0.w, e0.w, m0.w);
                z1.x = fmaf(s1.x, e1.x, m1.x); z1.y = fmaf(s1.y, e1.y, m1.y);
                z1.z = fmaf(s1.z, e1.z, m1.z); z1.w = fmaf(s1.w, e1.w, m1.w);
                if (seg == 0) {
                    float* sp = sig_t + rglob * ZZ + ks;
                    float* zp = z_t + rglob * ZZ + ks;
                    *reinterpret_cast<float4*>(sp) = s0;
                    *reinterpret_cast<float4*>(sp + 4) = s1;
                    *reinterpret_cast<float4*>(zp) = z0;
                    *reinterpret_cast<float4*>(zp + 4) = z1;
                }
                ra0 = z0; ra1 = z1;
            }
        } else {
            const float* s = hprev + (rbase + row) * NH + (k0 - kin) + (kh << 3);
            ra0 = *reinterpret_cast<const float4*>(s);
            ra1 = *reinterpret_cast<const float4*>(s + 4);
        }
    };

    auto do_store = [&](int p) {
        float* wb = wB + (p << 11);
        *reinterpret_cast<float4*>(wb + (wk << 6) + (fi << 2)) = rw0;
        *reinterpret_cast<float4*>(wb + ((wk + 8) << 6) + (fi << 2)) = rw1;
        *reinterpret_cast<float4*>(wb + ((wk + 16) << 6) + (fi << 2)) = rw2;
        *reinterpret_cast<float4*>(wb + ((wk + 24) << 6) + (fi << 2)) = rw3;
        ull* ab = aB + (p << 10);
        ull d;
        int b = (kh << 3) * 32 + row;
        asm("mov.b64 %0,{%1,%1};" : "=l"(d) : "f"(ra0.x)); ab[b] = d;
        asm("mov.b64 %0,{%1,%1};" : "=l"(d) : "f"(ra0.y)); ab[b + 32] = d;
        asm("mov.b64 %0,{%1,%1};" : "=l"(d) : "f"(ra0.z)); ab[b + 64] = d;
        asm("mov.b64 %0,{%1,%1};" : "=l"(d) : "f"(ra0.w)); ab[b + 96] = d;
        asm("mov.b64 %0,{%1,%1};" : "=l"(d) : "f"(ra1.x)); ab[b + 128] = d;
        asm("mov.b64 %0,{%1,%1};" : "=l"(d) : "f"(ra1.y)); ab[b + 160] = d;
        asm("mov.b64 %0,{%1,%1};" : "=l"(d) : "f"(ra1.z)); ab[b + 192] = d;
        asm("mov.b64 %0,{%1,%1};" : "=l"(d) : "f"(ra1.w)); ab[b + 224] = d;
    };

    ull acc[8];
    if (q == 0) {
        float bi = bias[hb + c];
        float bf = bias[NH + hb + c];
        float bc = bias[2 * NH + hb + c];
        float bo = bias[3 * NH + hb + c];
        ull b01, b23;
        asm("mov.b64 %0,{%1,%2};" : "=l"(b01) : "f"(bi), "f"(bf));
        asm("mov.b64 %0,{%1,%2};" : "=l"(b23) : "f"(bc), "f"(bo));
        acc[0] = acc[2] = acc[4] = acc[6] = b01;
        acc[1] = acc[3] = acc[5] = acc[7] = b23;
    } else {
#pragma unroll
        for (int i = 0; i < 8; i++) acc[i] = 0ULL;
    }

    auto compute = [&](int p) {
        const float* wb = wB + (p << 11);
        const ull* ab = aB + (p << 10);
#pragma unroll
        for (int kk = 0; kk < 32; kk++) {
            ulonglong2 wv = *reinterpret_cast<const ulonglong2*>(
                wb + (kk << 6) + (c << 2));
            ulonglong2 a01 = *reinterpret_cast<const ulonglong2*>(
                ab + (kk << 5) + (rg << 2));
            ulonglong2 a23 = *reinterpret_cast<const ulonglong2*>(
                ab + (kk << 5) + (rg << 2) + 2);
            FMA2(acc[0], wv.x, a01.x); FMA2(acc[1], wv.y, a01.x);
            FMA2(acc[2], wv.x, a01.y); FMA2(acc[3], wv.y, a01.y);
            FMA2(acc[4], wv.x, a23.x); FMA2(acc[5], wv.y, a23.x);
            FMA2(acc[6], wv.x, a23.y); FMA2(acc[7], wv.y, a23.y);
        }
    };

    const int nt = (kin + NH) >> 5;
    const int cntMax = (nt + 3) >> 2;

    do_load(q);
    do_store(0);
    __syncthreads();

    int p = 0;
    for (int i = 0; i < cntMax; i++) {
        bool have = (q + (i << 2)) < nt;
        bool haveNext = (i + 1 < cntMax) && ((q + ((i + 1) << 2)) < nt);
        if (haveNext) do_load(q + ((i + 1) << 2));
        if (have) compute(p);
        if (haveNext) do_store(p ^ 1);
        __syncthreads();
        p ^= 1;
    }

    // merge K-quarters + LSTM epilogue
    ull* ex = (ull*)smemPool;
    if (q) {
        int b = (((q - 1) << 7) + tq) << 3;
#pragma unroll
        for (int i = 0; i < 8; i++) ex[b + i] = acc[i];
    }
    __syncthreads();
    if (q == 0) {
#pragma unroll
        for (int qq = 0; qq < 3; qq++) {
            int b = ((qq << 7) + tq) << 3;
#pragma unroll
            for (int i = 0; i < 8; i++) {
                ull o = ex[b + i];
                asm("add.rn.f32x2 %0,%0,%1;" : "+l"(acc[i]) : "l"(o));
            }
        }
#pragma unroll
        for (int r = 0; r < 4; r++) {
            float gi, gf, gc, go;
            asm("mov.b64 {%0,%1},%2;" : "=f"(gi), "=f"(gf) : "l"(acc[2 * r]));
            asm("mov.b64 {%0,%1},%2;" : "=f"(gc), "=f"(go) : "l"(acc[2 * r + 1]));
            int idx = (rbase + (rg << 2) + r) * NH + hb + c;
            float cN = sigf(gf) * cst[idx] + sigf(gi) * tanhf(gc);
            cst[idx] = cN;
            hout[idx] = sigf(go) * tanhf(cN);
        }
    }
}

// ---------------- latent: mu / log_sigma (column-sliced) --------------------
__device__ __forceinline__ void latent_stage(
    const float* __restrict__ eh1,
    const float* __restrict__ muW, const float* __restrict__ mub,
    const float* __restrict__ sgW, const float* __restrict__ sgb,
    float* __restrict__ mu_t, float* __restrict__ ls_t, float* sAux)
{
    const int tid = threadIdx.x;
    const int rb = (blockIdx.x >> 5) << 5;
    const int cg = blockIdx.x & 31;
    const float* M; const float* bv; float* op; int cb;
    if (cg < 16) { M = muW; bv = mub; op = mu_t; cb = cg << 2; }
    else         { M = sgW; bv = sgb; op = ls_t; cb = (cg - 16) << 2; }
    const int r = tid >> 4, c2 = (tid >> 2) & 3, ks = tid & 3;
    const float* ar = eh1 + (rb + r) * NH + (ks << 7);
    const float* wc = M + ((ks << 7) * ZZ) + cb + c2;
    float acc = 0.f;
#pragma unroll 16
    for (int k = 0; k < 128; k++) acc = fmaf(ar[k], wc[k * ZZ], acc);
    sAux[tid] = acc;
    __syncthreads();
    if (tid < 128) {
        int r2 = tid >> 2, cc = tid & 3;
        int b0 = (r2 << 4) + (cc << 2);
        float v = sAux[b0] + sAux[b0 + 1] + sAux[b0 + 2] + sAux[b0 + 3]
                + bv[cb + cc];
        op[(rb + r2) * ZZ + cb + cc] = v;
    }
}

// ---------------- output: c_t = sigmoid(dh1 @ out_W + b) (column-sliced) ----
__device__ __forceinline__ void out_stage(
    const float* __restrict__ dh1,
    const float* __restrict__ oW, const float* __restrict__ ob,
    const float* __restrict__ x,
    float* __restrict__ decoded, int t, float* sAux)
{
    const int tid = threadIdx.x;
    const int rb = (blockIdx.x >> 5) << 5;
    const int cb = (blockIdx.x & 31) << 2;
    const int r = tid >> 4, c2 = (tid >> 2) & 3, ks = tid & 3;
    const float* ar = dh1 + (rb + r) * NH + (ks << 7);
    const float* wc = oW + ((ks << 7) * DD) + cb + c2;
    float acc = 0.f;
#pragma unroll 16
    for (int k = 0; k < 128; k++) acc = fmaf(ar[k], wc[k * DD], acc);
    sAux[tid] = acc;
    __syncthreads();
    if (tid < 128) {
        int r2 = tid >> 2, cc = tid & 3;
        int b0 = (r2 << 4) + (cc << 2);
        float v = sAux[b0] + sAux[b0 + 1] + sAux[b0 + 2] + sAux[b0 + 3]
                + ob[cb + cc];
        float ct = sigf(v);
        int rg = rb + r2, col = cb + cc;
        decoded[(rg * TT + t) * DD + col] = ct;
        if (t + 1 < TT) {
            float xv = x[(rg * TT + t + 1) * DD + col];
            g_encin[rg * 256 + col] = xv;
            g_encin[rg * 256 + DD + col] = xv - sigf(ct);
        }
    }
}

// ---------------- main persistent kernel ------------------------------------
__global__ void __launch_bounds__(512, 1) vae_kernel(
    const float* __restrict__ x, const float* __restrict__ eps,
    const float* __restrict__ e0W, const float* __restrict__ e0U, const float* __restrict__ e0b,
    const float* __restrict__ e1W, const float* __restrict__ e1U, const float* __restrict__ e1b,
    const float* __restrict__ muW, const float* __restrict__ mub,
    const float* __restrict__ sgW, const float* __restrict__ sgb,
    const float* __restrict__ d0W, const float* __restrict__ d0U, const float* __restrict__ d0b,
    const float* __restrict__ d1W, const float* __restrict__ d1U, const float* __restrict__ d1b,
    const float* __restrict__ oW, const float* __restrict__ ob,
    float* __restrict__ out)
{
    extern __shared__ float smemPool[];
    const int tid = threadIdx.x;

    // ---- one-time weight reorder: dst col = seg*64 + hidden*4 + gate -------
    {
        const float* srcs[8] = {e0W, e0U, e1W, e1U, d0W, d0U, d1W, d1U};
        const int rws[8] = {256, 512, 512, 512, 64, 512, 512, 512};
        int gt = blockIdx.x * 512 + tid;
        int base = 0;
        for (int s = 0; s < 8; s++) {
            const float* S = srcs[s];
            int n = rws[s] << 11;
            for (int idx = gt; idx < n; idx += 65536) {
                int row = idx >> 11, cp = idx & 2047;
                int sg2 = cp >> 6, w6 = cp & 63;
                int cc2 = w6 >> 2, qg = w6 & 3;
                g_wr[((base + row) << 11) + cp] =
                    S[(row << 11) + qg * NH + (sg2 << 4) + cc2];
            }
            base += rws[s];
        }
    }

    // ---- init states + t=0 encoder input ----
    {
        int r = blockIdx.x;
        for (int i = tid; i < NH; i += 512) {
#pragma unroll
            for (int s = 0; s < 4; s++) {
                g_h[s][0][r * NH + i] = 0.f;
                g_c[s][r * NH + i] = 0.f;
            }
        }
        if (tid < DD) {
            float xv = x[r * TT * DD + tid];
            g_encin[r * 256 + tid] = xv;
            g_encin[r * 256 + DD + tid] = xv - 0.5f;   // sigmoid(0)=0.5
        }
    }
    gsync();

    float* decoded = out;                         // [B,T,D]
    float* o_sig = out + BB * TT * DD;            // [T,B,Z]
    float* o_mu  = o_sig + TT * BB * ZZ;
    float* o_ls  = o_mu + TT * BB * ZZ;
    float* o_z   = o_ls + TT * BB * ZZ;

    const float* Gr_e0 = g_wr;
    const float* Gr_e1 = g_wr + 768 * 2048;
    const float* Gr_d0 = g_wr + 1792 * 2048;
    const float* Gr_d1 = g_wr + 2368 * 2048;

    for (int t = 0; t < TT; t++) {
        int po = t & 1, pn = po ^ 1;
        float* mu_t = o_mu + t * BB * ZZ;
        float* ls_t = o_ls + t * BB * ZZ;
        float* sg_t = o_sig + t * BB * ZZ;
        float* z_t  = o_z + t * BB * ZZ;

        lstm_stage(g_encin, 256, g_h[0][po], Gr_e0, e0b,
                   g_c[0], g_h[0][pn], smemPool,
                   false, 0, 0, 0, 0, 0);
        gsync();

        lstm_stage(g_h[0][pn], 512, g_h[1][po], Gr_e1, e1b,
                   g_c[1], g_h[1][pn], smemPool,
                   false, 0, 0, 0, 0, 0);
        gsync();

        latent_stage(g_h[1][pn], muW, mub, sgW, sgb, mu_t, ls_t, smemPool);
        gsync();

        lstm_stage(0, 64, g_h[2][po], Gr_d0, d0b,
                   g_c[2], g_h[2][pn], smemPool,
                   true, mu_t, ls_t, eps + t * BB * ZZ, sg_t, z_t);
        gsync();

        lstm_stage(g_h[2][pn], 512, g_h[3][po], Gr_d1, d1b,
                   g_c[3], g_h[3][pn], smemPool,
                   false, 0, 0, 0, 0, 0);
        gsync();

        out_stage(g_h[3][pn], oW, ob, x, decoded, t, smemPool);
        gsync();
    }
}

extern "C" void kernel_launch(void* const* d_in, const int* in_sizes, int n_in,
                              void* d_out, int out_size)
{
    (void)in_sizes; (void)n_in; (void)out_size;
    const int smemBytes = 131072;   // 4 quarters x (2x8KB w + 2x8KB aT)
    cudaFuncSetAttribute(vae_kernel,
                         cudaFuncAttributeMaxDynamicSharedMemorySize, smemBytes);
    vae_kernel<<<128, 512, smemBytes>>>(
        (const float*)d_in[0],  (const float*)d_in[1],
        (const float*)d_in[2],  (const float*)d_in[3],  (const float*)d_in[4],
        (const float*)d_in[5],  (const float*)d_in[6],  (const float*)d_in[7],
        (const float*)d_in[8],  (const float*)d_in[9],
        (const float*)d_in[10], (const float*)d_in[11],
        (const float*)d_in[12], (const float*)d_in[13], (const float*)d_in[14],
        (const float*)d_in[15], (const float*)d_in[16], (const float*)d_in[17],
        (const float*)d_in[18], (const float*)d_in[19],
        (float*)d_out);
}